// round 17
// baseline (speedup 1.0000x reference)
#include <cuda_runtime.h>
#include <cuda_bf16.h>
#include <cstdint>

// ---------------- constants ----------------
#define NB    2
#define CIN   64
#define CD    32
#define HHd   24
#define WWd   24
#define NP    4608          // 8*24*24
#define TF    16
#define HF    48
#define WF    48
#define NTOT  (32*NP)
#define KT    128
#define NKT   (NP/KT)       // 36
#define QSCALE 0.72134752044482f   // 0.5 * log2(e)

typedef unsigned long long u64;

// ---------------- scratch ----------------
__device__ __align__(16) u64 g_qhl[2*NB*NP*8];
__device__ __align__(16) u64 g_khl[2*NB*NP*8];
__device__ __align__(16) char g_vp[(size_t)2*NB*32*NP*2];
__device__ float g_ao [2][NB*32*NP];
__device__ float g_up [2][NB*64*NP];
__device__ float g_bsum[4][72][2];

// ---------------- helpers ----------------
__device__ __forceinline__ uint32_t smem_u32(const void* p) {
    uint32_t a;
    asm("{ .reg .u64 t; cvta.to.shared.u64 t, %1; cvt.u32.u64 %0, t; }" : "=r"(a) : "l"(p));
    return a;
}
__device__ __forceinline__ uint32_t pkb(__nv_bfloat16 lo, __nv_bfloat16 hi) {
    return ((uint32_t)__bfloat16_as_ushort(hi) << 16) | (uint32_t)__bfloat16_as_ushort(lo);
}
__device__ __forceinline__ uint32_t pkbf2(float lo, float hi) {
    uint32_t r;
    asm("cvt.rn.bf16x2.f32 %0, %1, %2;" : "=r"(r) : "f"(hi), "f"(lo));
    return r;
}
__device__ __forceinline__ float ex2f(float x) {
    float r;
    asm("ex2.approx.f32 %0, %1;" : "=f"(r) : "f"(x));
    return r;
}
__device__ __forceinline__ void mma_bf16(float* c, const uint32_t* a, uint32_t b0, uint32_t b1) {
    asm volatile(
        "mma.sync.aligned.m16n8k16.row.col.f32.bf16.bf16.f32 "
        "{%0,%1,%2,%3}, {%4,%5,%6,%7}, {%8,%9}, {%0,%1,%2,%3};"
        : "+f"(c[0]), "+f"(c[1]), "+f"(c[2]), "+f"(c[3])
        : "r"(a[0]), "r"(a[1]), "r"(a[2]), "r"(a[3]), "r"(b0), "r"(b1));
}
__device__ __forceinline__ void cpa16(uint32_t dst, const void* src) {
    asm volatile("cp.async.cg.shared.global [%0], [%1], 16;" :: "r"(dst), "l"(src) : "memory");
}
#define CP_COMMIT() asm volatile("cp.async.commit_group;" ::: "memory")
#define CP_WAIT1()  asm volatile("cp.async.wait_group 1;" ::: "memory")
#define CP_WAIT0()  asm volatile("cp.async.wait_group 0;" ::: "memory")

// packed store: slot i -> position ((i&3)<<1)|(i>>2)
__device__ __forceinline__ void store_hl16i(u64* d, const float* v) {
#pragma unroll
    for (int i = 0; i < 8; i++) {
        float v0 = v[2 * i], v1 = v[2 * i + 1];
        __nv_bfloat16 h0 = __float2bfloat16(v0);
        __nv_bfloat16 h1 = __float2bfloat16(v1);
        __nv_bfloat16 e0 = __float2bfloat16(v0 - __bfloat162float(h0));
        __nv_bfloat16 e1 = __float2bfloat16(v1 - __bfloat162float(h1));
        d[((i & 3) << 1) | (i >> 2)] = ((u64)pkb(e0, e1) << 32) | (u64)pkb(h0, h1);
    }
}
__device__ __forceinline__ void store_v(char* base_ab_ch, int p, float val) {
    int gi = p >> 4, r = p & 15;
    int ofs = ((r & 7) >> 1) * 8 + ((r >> 3) & 1) * 4 + (r & 1) * 2;
    *(__nv_bfloat16*)(base_ab_ch + (size_t)gi * 32 + ofs) = __float2bfloat16(val);
}

// ---------------- K1: fused resize + downconv + QKV/RoPE ----------------
// z=0: x -> xd -> q(cross)     [uses wd, wq; offsets: off]
// z=1: xc -> xcd -> k,v(cross, k uses offc) + q_sa,k_sa,v_sa(self, off)
__global__ __launch_bounds__(128) void k_prep(
    const float* __restrict__ x,   const float* __restrict__ xc,
    const float* __restrict__ wd,  const float* __restrict__ bd,
    const float* __restrict__ wdc, const float* __restrict__ bdc,
    const float* __restrict__ wq,  const float* __restrict__ bq,
    const float* __restrict__ wk,  const float* __restrict__ bk,
    const float* __restrict__ wv,  const float* __restrict__ bv,
    const float* __restrict__ wqs, const float* __restrict__ bqs,
    const float* __restrict__ wks, const float* __restrict__ bks,
    const float* __restrict__ wvs, const float* __restrict__ bvs,
    const float* __restrict__ off, const float* __restrict__ offc) {
    int z = blockIdx.z;
    __shared__ float s_conv[2048];
    __shared__ float s_a[512];    // wq (z0) / wk (z1)
    __shared__ float s_v1[1024];  // wv  (z1)
    __shared__ float s_qs[512];   // wqs (z1)
    __shared__ float s_ks[512];   // wks (z1)
    __shared__ float s_v2[1024];  // wvs (z1)
    __shared__ float sb_conv[32], sb_a[16], sb_v1[32], sb_qs[16], sb_ks[16], sb_v2[32];

    {
        const float* WC = z ? wdc : wd;
        const float* BC = z ? bdc : bd;
        const float* WA = z ? wk : wq;
        const float* BA = z ? bk : bq;
        for (int i = threadIdx.x; i < 2048; i += 128) s_conv[i] = WC[i];
        for (int i = threadIdx.x; i < 512; i += 128) s_a[i] = WA[i];
        if (threadIdx.x < 32) sb_conv[threadIdx.x] = BC[threadIdx.x];
        if (threadIdx.x < 16) sb_a[threadIdx.x] = BA[threadIdx.x];
        if (z) {
            for (int i = threadIdx.x; i < 1024; i += 128) { s_v1[i] = wv[i]; s_v2[i] = wvs[i]; }
            for (int i = threadIdx.x; i < 512; i += 128) { s_qs[i] = wqs[i]; s_ks[i] = wks[i]; }
            if (threadIdx.x < 32) { sb_v1[threadIdx.x] = bv[threadIdx.x]; sb_v2[threadIdx.x] = bvs[threadIdx.x]; }
            if (threadIdx.x < 16) { sb_qs[threadIdx.x] = bqs[threadIdx.x]; sb_ks[threadIdx.x] = bks[threadIdx.x]; }
        }
    }
    __syncthreads();

    int idx = blockIdx.x * 128 + threadIdx.x;   // < NB*NP
    int b = idx / NP, p = idx % NP;
    int wq_ = p % WWd, h = (p / WWd) % HHd, t = p / (WWd * HHd);

    float pt = (float)t * (15.0f / 7.0f);
    int t0 = (int)pt; float wt = pt - (float)t0; int t1 = min(t0 + 1, 15); t0 = min(t0, 15);
    float ph = (float)h * (47.0f / 23.0f);
    int h0 = (int)ph; float wh = ph - (float)h0; int h1 = min(h0 + 1, 47); h0 = min(h0, 47);
    float pw = (float)wq_ * (47.0f / 23.0f);
    int w0 = (int)pw; float ww = pw - (float)w0; int w1 = min(w0 + 1, 47); w0 = min(w0, 47);

    const float* src = z ? xc : x;
    const float* base = src + (size_t)b * (CIN * TF * HF * WF);
    int o00 = t0 * (HF * WF) + h0 * WF;
    int o01 = t0 * (HF * WF) + h1 * WF;
    int o10 = t1 * (HF * WF) + h0 * WF;
    int o11 = t1 * (HF * WF) + h1 * WF;

    float xin[CIN];
#pragma unroll 8
    for (int c = 0; c < CIN; c++) {
        const float* bc_ = base + (size_t)c * (TF * HF * WF);
        float c00 = __ldg(bc_ + o00 + w0); c00 += (__ldg(bc_ + o00 + w1) - c00) * ww;
        float c01 = __ldg(bc_ + o01 + w0); c01 += (__ldg(bc_ + o01 + w1) - c01) * ww;
        float c10 = __ldg(bc_ + o10 + w0); c10 += (__ldg(bc_ + o10 + w1) - c10) * ww;
        float c11 = __ldg(bc_ + o11 + w0); c11 += (__ldg(bc_ + o11 + w1) - c11) * ww;
        float c0 = c00 + (c01 - c00) * wh;
        float c1 = c10 + (c11 - c10) * wh;
        xin[c] = c0 + (c1 - c0) * wt;
    }
    float xd[CD];
#pragma unroll
    for (int o = 0; o < CD; o++) {
        float acc = sb_conv[o];
#pragma unroll
        for (int c = 0; c < CIN; c++) acc = fmaf(s_conv[o * CIN + c], xin[c], acc);
        xd[o] = acc;
    }

    const float invf[8] = {1.0f, 0.31622776601683794f, 0.1f, 0.031622776601683794f,
                           0.01f, 0.0031622776601683794f, 0.001f, 0.00031622776601683794f};
    float se[8], ce[8], sc_[8], cc_[8];
    float tf = (float)t;
#pragma unroll
    for (int i = 0; i < 8; i++) {
        float a = tf * invf[i];
        float s = sinf(a), c = cosf(a);
        float o1 = off[i * 500 + t];
        se[i] = s + o1; ce[i] = c + o1;          // same offset on sin AND cos (per reference)
        if (z) {
            float o2 = offc[i * 500 + t];
            sc_[i] = s + o2; cc_[i] = c + o2;    // cross-attn k offset
        }
    }

    float tmp[16], rv[16];

    if (z == 0) {
        // q (cross) -> ab = 0*NB+b
        int row = b * NP + p;
#pragma unroll
        for (int o = 0; o < 16; o++) {
            float acc = sb_a[o];
#pragma unroll
            for (int c = 0; c < CD; c++) acc = fmaf(s_a[o * CD + c], xd[c], acc);
            tmp[o] = acc;
        }
#pragma unroll
        for (int i = 0; i < 8; i++) {
            rv[i]     = QSCALE * (tmp[i] * ce[i] - tmp[8 + i] * se[i]);
            rv[8 + i] = QSCALE * (tmp[8 + i] * ce[i] + tmp[i] * se[i]);
        }
        store_hl16i(g_qhl + (size_t)row * 8, rv);
    } else {
        int row0 = b * NP + p;                 // ab = 0 (cross)
        int row1 = (NB + b) * NP + p;          // ab = 1 (self)
        // k (cross), rope offc
#pragma unroll
        for (int o = 0; o < 16; o++) {
            float acc = sb_a[o];
#pragma unroll
            for (int c = 0; c < CD; c++) acc = fmaf(s_a[o * CD + c], xd[c], acc);
            tmp[o] = acc;
        }
#pragma unroll
        for (int i = 0; i < 8; i++) {
            rv[i]     = tmp[i] * cc_[i] - tmp[8 + i] * sc_[i];
            rv[8 + i] = tmp[8 + i] * cc_[i] + tmp[i] * sc_[i];
        }
        store_hl16i(g_khl + (size_t)row0 * 8, rv);
        // v (cross)
#pragma unroll
        for (int o = 0; o < 32; o++) {
            float acc = sb_v1[o];
#pragma unroll
            for (int c = 0; c < CD; c++) acc = fmaf(s_v1[o * CD + c], xd[c], acc);
            store_v(g_vp + (size_t)(0 * NB * 32 + b * 32 + o) * (NP * 2), p, acc);
        }
        // q_sa, rope off, scaled
#pragma unroll
        for (int o = 0; o < 16; o++) {
            float acc = sb_qs[o];
#pragma unroll
            for (int c = 0; c < CD; c++) acc = fmaf(s_qs[o * CD + c], xd[c], acc);
            tmp[o] = acc;
        }
#pragma unroll
        for (int i = 0; i < 8; i++) {
            rv[i]     = QSCALE * (tmp[i] * ce[i] - tmp[8 + i] * se[i]);
            rv[8 + i] = QSCALE * (tmp[8 + i] * ce[i] + tmp[i] * se[i]);
        }
        store_hl16i(g_qhl + (size_t)row1 * 8, rv);
        // k_sa, rope off
#pragma unroll
        for (int o = 0; o < 16; o++) {
            float acc = sb_ks[o];
#pragma unroll
            for (int c = 0; c < CD; c++) acc = fmaf(s_ks[o * CD + c], xd[c], acc);
            tmp[o] = acc;
        }
#pragma unroll
        for (int i = 0; i < 8; i++) {
            rv[i]     = tmp[i] * ce[i] - tmp[8 + i] * se[i];
            rv[8 + i] = tmp[8 + i] * ce[i] + tmp[i] * se[i];
        }
        store_hl16i(g_khl + (size_t)row1 * 8, rv);
        // v_sa
#pragma unroll
        for (int o = 0; o < 32; o++) {
            float acc = sb_v2[o];
#pragma unroll
            for (int c = 0; c < CD; c++) acc = fmaf(s_v2[o * CD + c], xd[c], acc);
            store_v(g_vp + (size_t)(1 * NB * 32 + b * 32 + o) * (NP * 2), p, acc);
        }
    }
}

// ---------------- K2: single-pass shift-free FA mma.sync attention + GN stats ----------------
__device__ __forceinline__ void stage_tile(const char* gk, const char* gv,
                                           uint32_t skb, uint32_t svb,
                                           int tid, int tile, int buf) {
    const char* ks = gk + (size_t)tile * 8192;
    uint32_t kd = skb + (uint32_t)buf * 8192;
#pragma unroll
    for (int n = 0; n < 4; n++) {
        uint32_t off = (uint32_t)(tid + n * 128) * 16;
        uint32_t key = off >> 6;
        cpa16(kd + (off ^ ((key & 3) << 5)), ks + off);
    }
    const char* vs = gv + (size_t)tile * 256;
    uint32_t vd = svb + (uint32_t)buf * 8192;
#pragma unroll
    for (int n = 0; n < 4; n++) {
        int w = tid + n * 128;
        int ch = w >> 4, wi = w & 15;
        uint32_t off = (uint32_t)(ch * 256 + wi * 16);
        cpa16(vd + (off ^ (((uint32_t)ch & 3) << 5)), vs + (size_t)ch * (NP * 2) + wi * 16);
    }
}

__global__ __launch_bounds__(128) void k_attn() {
    __shared__ __align__(128) char sKs[2][8192];
    __shared__ __align__(128) char sVs[2][8192];
    __shared__ float rs1[128], rs2[128];
    int a = blockIdx.z;
    int b = blockIdx.y;
    int ab = a * NB + b;
    int tid = threadIdx.x;
    int wid = tid >> 5, lane = tid & 31;
    int g = lane >> 2, t = lane & 3;
    int q0 = blockIdx.x * 64 + wid * 16;

    const u64* QHL = g_qhl + (size_t)ab * NP * 8;
    const char* gk = (const char*)(g_khl + (size_t)ab * NP * 8);
    const char* gv = g_vp + (size_t)ab * 32 * (NP * 2);
    float* O = g_ao[a] + b * 32 * NP;

    uint32_t skb = smem_u32(sKs);
    uint32_t svb = smem_u32(sVs);
    uint32_t swz = ((uint32_t)g & 3) << 5;

    uint32_t qh[4], ql[4];
    {
        int r0 = q0 + g, r1 = r0 + 8;
        u64 w0 = QHL[r0 * 8 + 2 * t];
        u64 w2 = QHL[r0 * 8 + 2 * t + 1];
        u64 w1 = QHL[r1 * 8 + 2 * t];
        u64 w3 = QHL[r1 * 8 + 2 * t + 1];
        qh[0] = (uint32_t)w0; ql[0] = (uint32_t)(w0 >> 32);
        qh[1] = (uint32_t)w1; ql[1] = (uint32_t)(w1 >> 32);
        qh[2] = (uint32_t)w2; ql[2] = (uint32_t)(w2 >> 32);
        qh[3] = (uint32_t)w3; ql[3] = (uint32_t)(w3 >> 32);
    }

    float oacc[16];
#pragma unroll
    for (int i = 0; i < 16; i++) oacc[i] = 0.0f;
    float ls0 = 0.0f, ls1 = 0.0f;

    stage_tile(gk, gv, skb, svb, tid, 0, 0);
    CP_COMMIT();

    for (int kk = 0; kk < NKT; kk++) {
        int buf = kk & 1;
        if (kk + 1 < NKT) {
            stage_tile(gk, gv, skb, svb, tid, kk + 1, (kk + 1) & 1);
            CP_COMMIT();
            CP_WAIT1();
        } else {
            CP_WAIT0();
        }
        __syncthreads();

        uint32_t kb = skb + (uint32_t)buf * 8192;
        uint32_t vbb = svb + (uint32_t)buf * 8192;

#pragma unroll
        for (int half = 0; half < 2; half++) {
            float acc[8][4];
#pragma unroll
            for (int j = 0; j < 8; j++) {
                acc[j][0] = acc[j][1] = acc[j][2] = acc[j][3] = 0.0f;
            }
#pragma unroll
            for (int j = 0; j < 8; j++) {
                uint32_t row = (uint32_t)(half * 64 + 8 * j + g) * 64 + (uint32_t)t * 16;
                uint32_t addr = kb + (row ^ swz);
                uint32_t b0h, b0l, b1h, b1l;
                asm("ld.shared.v4.b32 {%0,%1,%2,%3}, [%4];"
                    : "=r"(b0h), "=r"(b0l), "=r"(b1h), "=r"(b1l) : "r"(addr));
                mma_bf16(acc[j], qh, b0h, b1h);
                mma_bf16(acc[j], ql, b0h, b1h);
                mma_bf16(acc[j], qh, b0l, b1l);
            }
#pragma unroll
            for (int kc = 0; kc < 4; kc++) {
                float p0 = ex2f(acc[2 * kc][0]);
                float p1 = ex2f(acc[2 * kc][1]);
                float p2 = ex2f(acc[2 * kc][2]);
                float p3 = ex2f(acc[2 * kc][3]);
                float p4 = ex2f(acc[2 * kc + 1][0]);
                float p5 = ex2f(acc[2 * kc + 1][1]);
                float p6 = ex2f(acc[2 * kc + 1][2]);
                float p7 = ex2f(acc[2 * kc + 1][3]);
                ls0 += (p0 + p1) + (p4 + p5);
                ls1 += (p2 + p3) + (p6 + p7);
                uint32_t pa[4] = { pkbf2(p0, p1), pkbf2(p2, p3), pkbf2(p4, p5), pkbf2(p6, p7) };
#pragma unroll
                for (int j2 = 0; j2 < 4; j2++) {
                    uint32_t off = (uint32_t)((8 * j2 + g) * 256 + (half * 4 + kc) * 32 + t * 8);
                    uint32_t addr = vbb + (off ^ swz);
                    uint32_t vb0, vb1;
                    asm("ld.shared.v2.b32 {%0,%1}, [%2];" : "=r"(vb0), "=r"(vb1) : "r"(addr));
                    mma_bf16(&oacc[4 * j2], pa, vb0, vb1);
                }
            }
        }
        __syncthreads();
    }

    float l0 = ls0;
    l0 += __shfl_xor_sync(0xffffffffu, l0, 1);
    l0 += __shfl_xor_sync(0xffffffffu, l0, 2);
    float l1 = ls1;
    l1 += __shfl_xor_sync(0xffffffffu, l1, 1);
    l1 += __shfl_xor_sync(0xffffffffu, l1, 2);
    float inv0 = 1.0f / l0, inv1 = 1.0f / l1;

    float ts1 = 0.0f, ts2 = 0.0f;
    int r0 = q0 + g, r1 = r0 + 8;
#pragma unroll
    for (int j2 = 0; j2 < 4; j2++) {
        int ch = 8 * j2 + 2 * t;
        float v0 = oacc[4 * j2 + 0] * inv0;
        float v1 = oacc[4 * j2 + 1] * inv0;
        float v2 = oacc[4 * j2 + 2] * inv1;
        float v3 = oacc[4 * j2 + 3] * inv1;
        O[ch * NP + r0]       = v0;
        O[(ch + 1) * NP + r0] = v1;
        O[ch * NP + r1]       = v2;
        O[(ch + 1) * NP + r1] = v3;
        ts1 += (v0 + v1) + (v2 + v3);
        ts2 += fmaf(v0, v0, fmaf(v1, v1, fmaf(v2, v2, v3 * v3)));
    }
    rs1[tid] = ts1; rs2[tid] = ts2;
    __syncthreads();
    for (int s = 64; s > 0; s >>= 1) {
        if (tid < s) { rs1[tid] += rs1[tid + s]; rs2[tid] += rs2[tid + s]; }
        __syncthreads();
    }
    if (tid == 0) {
        g_bsum[ab][blockIdx.x][0] = rs1[0];
        g_bsum[ab][blockIdx.x][1] = rs2[0];
    }
}

// ---------------- K3: groupnorm apply + up conv 32 -> 64 ----------------
__global__ __launch_bounds__(128) void k_gnup(
    const float* __restrict__ gnw,  const float* __restrict__ gnb,
    const float* __restrict__ gnws, const float* __restrict__ gnbs,
    const float* __restrict__ wup,  const float* __restrict__ bup,
    const float* __restrict__ wups, const float* __restrict__ bups) {
    int a = blockIdx.z, b = blockIdx.y;
    int gb = a * 2 + b;
    __shared__ float sw[64 * 32];
    __shared__ float sb2[64], sa_[32], sd_[32];
    const float* w   = a ? wups : wup;
    const float* bb  = a ? bups : bup;
    const float* gw  = a ? gnws : gnw;
    const float* gbb = a ? gnbs : gnb;
    double s1 = 0.0, s2 = 0.0;
#pragma unroll
    for (int c = 0; c < 72; c++) { s1 += (double)g_bsum[gb][c][0]; s2 += (double)g_bsum[gb][c][1]; }
    double mu_d  = s1 / (double)NTOT;
    double var_d = s2 / (double)NTOT - mu_d * mu_d;
    float mu = (float)mu_d;
    float rstd = rsqrtf((float)var_d + 1e-5f);
    for (int i = threadIdx.x; i < 2048; i += 128) sw[i] = w[i];
    if (threadIdx.x < 64) sb2[threadIdx.x] = bb[threadIdx.x];
    if (threadIdx.x < 32) {
        float aa = rstd * gw[threadIdx.x];
        sa_[threadIdx.x] = aa;
        sd_[threadIdx.x] = gbb[threadIdx.x] - mu * aa;
    }
    __syncthreads();
    int p = blockIdx.x * 128 + threadIdx.x;
    const float* src = g_ao[a] + b * 32 * NP;
    float xn[32];
#pragma unroll
    for (int c = 0; c < 32; c++) xn[c] = fmaf(src[c * NP + p], sa_[c], sd_[c]);
    float* dst = g_up[a] + b * 64 * NP;
#pragma unroll
    for (int o = 0; o < 64; o++) {
        float acc = sb2[o];
#pragma unroll
        for (int c = 0; c < 32; c++) acc = fmaf(sw[o * 32 + c], xn[c], acc);
        dst[o * NP + p] = acc;
    }
}

// ---------------- K4: upsample + combine ----------------
__device__ __forceinline__ float tri8(const float* __restrict__ s,
                                      int p00, int p01, int p10, int p11,
                                      int w0, int w1, float ww, float wh, float wt) {
    float c00 = s[p00 + w0]; c00 += (s[p00 + w1] - c00) * ww;
    float c01 = s[p01 + w0]; c01 += (s[p01 + w1] - c01) * ww;
    float c10 = s[p10 + w0]; c10 += (s[p10 + w1] - c10) * ww;
    float c11 = s[p11 + w0]; c11 += (s[p11 + w1] - c11) * ww;
    float c0 = c00 + (c01 - c00) * wh;
    float c1 = c10 + (c11 - c10) * wh;
    return c0 + (c1 - c0) * wt;
}

__global__ void k_final(const float* __restrict__ xc, float* __restrict__ out) {
    int idx = blockIdx.x * 256 + threadIdx.x;
    int w = idx % WF;
    int h = (idx / WF) % HF;
    int t = (idx / (WF * HF)) % TF;
    int bc = idx / (WF * HF * TF);

    float pt = (float)t * (7.0f / 15.0f);
    int t0 = (int)pt; float wt = pt - (float)t0; int t1 = min(t0 + 1, 7); t0 = min(t0, 7);
    float ph = (float)h * (23.0f / 47.0f);
    int h0 = (int)ph; float wh = ph - (float)h0; int h1 = min(h0 + 1, 23); h0 = min(h0, 23);
    float pw = (float)w * (23.0f / 47.0f);
    int w0 = (int)pw; float ww = pw - (float)w0; int w1 = min(w0 + 1, 23); w0 = min(w0, 23);

    int base = bc * NP;
    int p00 = t0 * (HHd * WWd) + h0 * WWd;
    int p01 = t0 * (HHd * WWd) + h1 * WWd;
    int p10 = t1 * (HHd * WWd) + h0 * WWd;
    int p11 = t1 * (HHd * WWd) + h1 * WWd;

    float r_cross = tri8(g_up[0] + base, p00, p01, p10, p11, w0, w1, ww, wh, wt);
    float r_self  = tri8(g_up[1] + base, p00, p01, p10, p11, w0, w1, ww, wh, wt);
    out[idx] = r_self + xc[idx] - 0.5f * r_cross;
}

// ---------------- launch ----------------
extern "C" void kernel_launch(void* const* d_in, const int* in_sizes, int n_in,
                              void* d_out, int out_size) {
    const float* x       = (const float*)d_in[0];
    const float* x_c     = (const float*)d_in[1];
    const float* w_down  = (const float*)d_in[2];
    const float* b_down  = (const float*)d_in[3];
    const float* w_downc = (const float*)d_in[4];
    const float* b_downc = (const float*)d_in[5];
    const float* w_q     = (const float*)d_in[6];
    const float* b_q     = (const float*)d_in[7];
    const float* w_k     = (const float*)d_in[8];
    const float* b_k     = (const float*)d_in[9];
    const float* w_v     = (const float*)d_in[10];
    const float* b_v     = (const float*)d_in[11];
    const float* w_qsa   = (const float*)d_in[12];
    const float* b_qsa   = (const float*)d_in[13];
    const float* w_ksa   = (const float*)d_in[14];
    const float* b_ksa   = (const float*)d_in[15];
    const float* w_vsa   = (const float*)d_in[16];
    const float* b_vsa   = (const float*)d_in[17];
    const float* gn_w    = (const float*)d_in[18];
    const float* gn_b    = (const float*)d_in[19];
    const float* gn_wsa  = (const float*)d_in[20];
    const float* gn_bsa  = (const float*)d_in[21];
    const float* w_up    = (const float*)d_in[22];
    const float* b_up    = (const float*)d_in[23];
    const float* w_upsa  = (const float*)d_in[24];
    const float* b_upsa  = (const float*)d_in[25];
    const float* offset  = (const float*)d_in[26];
    const float* offsetc = (const float*)d_in[27];

    dim3 g1(72, 1, 2);
    k_prep<<<g1, 128>>>(x, x_c, w_down, b_down, w_downc, b_downc,
                        w_q, b_q, w_k, b_k, w_v, b_v,
                        w_qsa, b_qsa, w_ksa, b_ksa, w_vsa, b_vsa,
                        offset, offsetc);

    dim3 g4(72, NB, 2);
    k_attn<<<g4, 128>>>();

    dim3 g6(36, NB, 2);
    k_gnup<<<g6, 128>>>(gn_w, gn_b, gn_wsa, gn_bsa, w_up, b_up, w_upsa, b_upsa);

    k_final<<<18432, 256>>>(x_c, (float*)d_out);
}